// round 14
// baseline (speedup 1.0000x reference)
#include <cuda_runtime.h>
#include <cuda_fp16.h>
#include <cstdint>

#define BB 4
#define NN 4096
#define CC 64
#define OROWS 64           // o-tile rows
#define TI 128             // i rows per block
#define TJ 256             // j per stage (4 producer halves)
#define NST (NN / TJ)      // 16 stages
#define NBUF 2
#define NTHR 512

// smem row: 256 halves data + 8 pad = 264 halves = 528 B (528 mod 128 = 16)
#define ROWB 528
#define W_BYTES (TI * ROWB)               // 67584
#define O_BYTES (OROWS * ROWB)            // 33792
#define STG_B (W_BYTES + O_BYTES)         // 101376 per stage
#define SM_W2B  (NBUF * STG_B)            // 202752
#define SM_ZSHB (SM_W2B + 16384)          // 219136
#define SMEM_BYTES (SM_ZSHB + 512)        // 219648 (< 228 KB)

__device__ __half g_outT[BB * OROWS * NN]; // [b][c][n] half
__device__ float  g_sl[BB * NN];
__device__ float  g_sr[BB * NN];

__device__ __forceinline__ float ex2f(float x) {
    float r;
    asm("ex2.approx.f32 %0, %1;" : "=f"(r) : "f"(x));
    return r;
}
__device__ __forceinline__ uint32_t smem_u32(const void* p) {
    uint32_t a;
    asm("{ .reg .u64 t; cvta.to.shared.u64 t, %1; cvt.u32.u64 %0, t; }" : "=r"(a) : "l"(p));
    return a;
}
__device__ __forceinline__ void mma_f16(float d[4], const uint32_t a[4],
                                        uint32_t b0, uint32_t b1) {
    asm volatile(
        "mma.sync.aligned.m16n8k16.row.col.f32.f16.f16.f32 "
        "{%0,%1,%2,%3},{%4,%5,%6,%7},{%8,%9},{%0,%1,%2,%3};"
        : "+f"(d[0]), "+f"(d[1]), "+f"(d[2]), "+f"(d[3])
        : "r"(a[0]), "r"(a[1]), "r"(a[2]), "r"(a[3]), "r"(b0), "r"(b1));
}
#define LDSM4(r, a) \
    asm volatile("ldmatrix.sync.aligned.m8n8.x4.shared.b16 {%0,%1,%2,%3}, [%4];" \
        : "=r"((r)[0]), "=r"((r)[1]), "=r"((r)[2]), "=r"((r)[3]) : "r"(a))
#define BAR_SYNC(id)   asm volatile("bar.sync %0, 512;"   :: "r"(id) : "memory")
#define BAR_ARRIVE(id) asm volatile("bar.arrive %0, 512;" :: "r"(id) : "memory")
#define CP_ASYNC16(dst, src) \
    asm volatile("cp.async.cg.shared.global [%0], [%1], 16;" :: "r"(dst), "l"(src) : "memory")
#define CP_COMMIT() asm volatile("cp.async.commit_group;" ::: "memory")
#define CP_WAIT0()  asm volatile("cp.async.wait_group 0;" ::: "memory")

// ---------------------------------------------------------------------------
// prep: out = X@W1; g_outT = half(out) transposed via smem (coalesced); sl, sr
// ---------------------------------------------------------------------------
#define HBUF_STRIDE 136    // halves per c-row (128 + 8 pad)
#define PREP_SMEM_FLOATS (4096 + 128 * 65 + 128 + (64 * HBUF_STRIDE) / 2 + 8)
__global__ __launch_bounds__(256) void prep_kernel(
    const float* __restrict__ X, const float* __restrict__ W1,
    const float* __restrict__ alpha)
{
    extern __shared__ float psm[];
    float*  W1s  = psm;
    float*  Xs   = psm + 4096;
    float*  al   = psm + 4096 + 128 * 65;
    float*  ar   = al + 64;
    __half* hbuf = reinterpret_cast<__half*>(ar + 64);

    const int tid = threadIdx.x;
    const int gr0 = blockIdx.x * 128;
    const int b0  = gr0 >> 12;
    const int n0  = gr0 & (NN - 1);

    for (int i = tid; i < 1024; i += 256)
        reinterpret_cast<float4*>(W1s)[i] = reinterpret_cast<const float4*>(W1)[i];
    for (int i = tid; i < 2048; i += 256) {
        int r = i >> 4, q = i & 15;
        float4 v = reinterpret_cast<const float4*>(X + (size_t)(gr0 + r) * CC)[q];
        Xs[r * 65 + 4 * q + 0] = v.x; Xs[r * 65 + 4 * q + 1] = v.y;
        Xs[r * 65 + 4 * q + 2] = v.z; Xs[r * 65 + 4 * q + 3] = v.w;
    }
    if (tid < 64)       al[tid]      = alpha[tid];
    else if (tid < 128) ar[tid - 64] = alpha[tid];
    __syncthreads();

    const int r  = tid >> 2;
    const int c0 = tid & 3;

    float acc0[16], acc1[16];
#pragma unroll
    for (int q = 0; q < 16; q++) { acc0[q] = 0.f; acc1[q] = 0.f; }
    const float4* W1v = reinterpret_cast<const float4*>(W1s);
#pragma unroll 4
    for (int k = 0; k < 64; k++) {
        float x0 = Xs[r * 65 + k];
        float x1 = Xs[(r + 64) * 65 + k];
#pragma unroll
        for (int h = 0; h < 4; h++) {
            float4 wv = W1v[k * 16 + 4 * c0 + h];
            acc0[4 * h + 0] += x0 * wv.x; acc1[4 * h + 0] += x1 * wv.x;
            acc0[4 * h + 1] += x0 * wv.y; acc1[4 * h + 1] += x1 * wv.y;
            acc0[4 * h + 2] += x0 * wv.z; acc1[4 * h + 2] += x1 * wv.z;
            acc0[4 * h + 3] += x0 * wv.w; acc1[4 * h + 3] += x1 * wv.w;
        }
    }

    float vl0 = 0.f, vr0 = 0.f, vl1 = 0.f, vr1 = 0.f;
#pragma unroll
    for (int q = 0; q < 16; q++) {
        float a_ = al[16 * c0 + q], r_ = ar[16 * c0 + q];
        vl0 += acc0[q] * a_; vr0 += acc0[q] * r_;
        vl1 += acc1[q] * a_; vr1 += acc1[q] * r_;
    }
#pragma unroll
    for (int o = 1; o <= 2; o <<= 1) {
        vl0 += __shfl_xor_sync(0xffffffffu, vl0, o);
        vr0 += __shfl_xor_sync(0xffffffffu, vr0, o);
        vl1 += __shfl_xor_sync(0xffffffffu, vl1, o);
        vr1 += __shfl_xor_sync(0xffffffffu, vr1, o);
    }
    if (c0 == 0) {
        g_sl[gr0 + r] = vl0;       g_sr[gr0 + r] = vr0;
        g_sl[gr0 + r + 64] = vl1;  g_sr[gr0 + r + 64] = vr1;
    }

    // stage transposed halves in smem: hbuf[c][n] (n local 0..127)
#pragma unroll
    for (int q = 0; q < 16; q++) {
        int c = 16 * c0 + q;
        hbuf[c * HBUF_STRIDE + r]      = __float2half_rn(acc0[q]);
        hbuf[c * HBUF_STRIDE + r + 64] = __float2half_rn(acc1[q]);
    }
    __syncthreads();

    // coalesced write: 64 c-rows x 128 halves = 1024 uint4 chunks
    __half* oT = g_outT + (size_t)b0 * OROWS * NN + n0;
#pragma unroll
    for (int p = 0; p < 4; p++) {
        int i = tid + 256 * p;          // 0..1023
        int c = i >> 4, q = i & 15;     // q: 8-half (16B) chunk
        uint4 v = *reinterpret_cast<const uint4*>(hbuf + c * HBUF_STRIDE + 8 * q);
        *reinterpret_cast<uint4*>(oT + (size_t)c * NN + 8 * q) = v;
    }
}

// ---------------------------------------------------------------------------
// attn: fp16 mma + ldmatrix, TI=128 / TJ=256 (16 stages, 4 producer halves).
// 512 threads: warps 0..7 consumers (4 wm x 2 wn, nt=4), 8..15 producers.
// barrier ids: full = 1+buf (1..2), empty = 3+buf (3..4)
// ---------------------------------------------------------------------------
__device__ __forceinline__ void consume_tile(
    uint32_t wA, uint32_t wB, float acc[2][4][4])
{
#pragma unroll
    for (int ks = 0; ks < 16; ks++) {
        const uint32_t ko = (uint32_t)ks * 32;
        uint32_t a0[4], a1[4], bb[8];
        LDSM4(a0, wA + ko);
        LDSM4(a1, wA + 16 * ROWB + ko);     // +16 rows
        LDSM4(bb + 0, wB + ko);             // nt 0,1
        LDSM4(bb + 4, wB + 16 * ROWB + ko); // nt 2,3
#pragma unroll
        for (int nt = 0; nt < 4; nt++) {
            mma_f16(acc[0][nt], a0, bb[2 * nt], bb[2 * nt + 1]);
            mma_f16(acc[1][nt], a1, bb[2 * nt], bb[2 * nt + 1]);
        }
    }
}

__global__ void __launch_bounds__(NTHR, 1) attn_kernel(
    const float* __restrict__ A_, const float* __restrict__ W2,
    float* __restrict__ out)
{
    extern __shared__ char sm[];
    const uint32_t smb = smem_u32(sm);
    float* W2s = reinterpret_cast<float*>(sm + SM_W2B);
    float* Zsh = reinterpret_cast<float*>(sm + SM_ZSHB);

    const int b      = blockIdx.y;
    const int i_base = blockIdx.x * TI;
    const int tid    = threadIdx.x;

    for (int i = tid; i < 1024; i += NTHR)
        reinterpret_cast<float4*>(W2s)[i] = reinterpret_cast<const float4*>(W2)[i];
    __syncthreads();

    if (tid < 256) {
        // ---------------- consumers (8 warps) ----------------
        const int lane = tid & 31, wid = tid >> 5;
        const int wm = wid & 3, wn = wid >> 2;
        const int r = lane >> 2, cq = lane & 3;
        const int moff = wm * 32, noff = wn * 32;

        const uint32_t aoff = (uint32_t)((lane & 15) * ROWB + (lane >> 4) * 16);
        const uint32_t boff = (uint32_t)((((lane & 7) + ((lane >> 4) & 1) * 8)) * ROWB
                                         + ((lane >> 3) & 1) * 16);

        const uint32_t wA = smb + (uint32_t)moff * ROWB + aoff;
        const uint32_t wB = smb + W_BYTES + (uint32_t)noff * ROWB + boff;

        float acc[2][4][4];
#pragma unroll
        for (int mt = 0; mt < 2; mt++)
#pragma unroll
            for (int nt = 0; nt < 4; nt++)
#pragma unroll
                for (int e = 0; e < 4; e++) acc[mt][nt][e] = 0.f;

        for (int s = 0; s < NST; s++) {
            const int buf = s & 1;
            BAR_SYNC(1 + buf);
            const uint32_t bo = (uint32_t)buf * STG_B;
            consume_tile(wA + bo, wB + bo, acc);
            BAR_ARRIVE(3 + buf);
        }

        __syncthreads();   // (A) -- producers have written Zsh

        float* aggS = reinterpret_cast<float*>(sm);   // 128 x 68 fp32
#pragma unroll
        for (int mt = 0; mt < 2; mt++) {
            int rr = moff + mt * 16 + r;
            float z0 = 1.0f / Zsh[rr];
            float z1 = 1.0f / Zsh[rr + 8];
#pragma unroll
            for (int nt = 0; nt < 4; nt++) {
                int col = noff + nt * 8 + 2 * cq;
                aggS[rr * 68 + col]           = acc[mt][nt][0] * z0;
                aggS[rr * 68 + col + 1]       = acc[mt][nt][1] * z0;
                aggS[(rr + 8) * 68 + col]     = acc[mt][nt][2] * z1;
                aggS[(rr + 8) * 68 + col + 1] = acc[mt][nt][3] * z1;
            }
        }
    } else {
        // ---------------- producers (8 warps, 256 threads) ----------------
        const int ptid = tid - 256;
        const int jj8  = ptid & 7;          // 8-col group within a 64-wide half
        const int rgrp = ptid >> 3;         // rows rgrp + 32k, k<4

        const float*  Abase = A_ + (size_t)(i_base + rgrp) * NN + 8 * jj8;
        const __half* oTb   = g_outT + (size_t)b * OROWS * NN;
        const float*  srb   = g_sr + b * NN + 8 * jj8;

        float cl[4];
        unsigned fl[4];
#pragma unroll
        for (int k = 0; k < 4; k++) {
            float s_ = g_sl[b * NN + i_base + rgrp + 32 * k];
            fl[k] = (s_ > 0.f);
            cl[k] = fabsf(s_) * 1.44269504f;
        }

        // o-tile cp.async: 64 rows x 32 chunks (16B) = 2048 -> 8 per thread
        uint32_t odst[8];
        int      osrc[8];
#pragma unroll
        for (int p = 0; p < 8; p++) {
            int it = ptid + 256 * p;
            int rr = it >> 5, q = it & 31;
            odst[p] = (uint32_t)(rr * ROWB + 16 * q);
            osrc[p] = rr * NN + 8 * q;
        }

        // diagonal: stage dstage, halves h0 (rows 0..63) and h0+1 (rows 64..127)
        const int dstage = i_base / TJ;
        const int h0     = (i_base >> 6) & 3;

        float zacc[4] = {0.f, 0.f, 0.f, 0.f};
        float4 a4[4][2];
        float  srv[8];

        auto load_half = [&](int jb, int h) {
            const int off = jb + 64 * h;
#pragma unroll
            for (int k = 0; k < 4; k++) {
                a4[k][0] = *reinterpret_cast<const float4*>(Abase + (size_t)(32 * k) * NN + off);
                a4[k][1] = *reinterpret_cast<const float4*>(Abase + (size_t)(32 * k) * NN + off + 4);
            }
            float4 s0 = *reinterpret_cast<const float4*>(srb + off);
            float4 s1 = *reinterpret_cast<const float4*>(srb + off + 4);
            srv[0] = s0.x; srv[1] = s0.y; srv[2] = s0.z; srv[3] = s0.w;
            srv[4] = s1.x; srv[5] = s1.y; srv[6] = s1.z; srv[7] = s1.w;
        };

        auto compute_half = [&](int h, int s, uint4* wu) {
            if (s == dstage && (h == h0 || h == h0 + 1)) {
                const int kbase = (h == h0) ? 0 : 2;
#pragma unroll
                for (int kk = 0; kk < 2; kk++) {
                    int colh = rgrp + 32 * kk;   // diag col within this half
                    if ((colh >> 3) == jj8)
                        reinterpret_cast<float*>(&a4[kbase + kk][0])[colh & 7] = 1.0f;
                }
            }
            float lp[8], lm[8];
#pragma unroll
            for (int e = 0; e < 8; e++) {
                lp[e] = fmaxf(srv[e], 0.01f * srv[e]);
                lm[e] = fmaxf(-srv[e], -0.01f * srv[e]);
            }
#pragma unroll
            for (int k = 0; k < 4; k++) {
                const float* av = reinterpret_cast<const float*>(&a4[k][0]);
                const int row = rgrp + 32 * k;
                uint32_t hh[4];
#pragma unroll
                for (int e2 = 0; e2 < 4; e2++) {
                    float t0 = cl[k] * (fl[k] ? lp[2 * e2]     : lm[2 * e2]);
                    float t1 = cl[k] * (fl[k] ? lp[2 * e2 + 1] : lm[2 * e2 + 1]);
                    float f0 = ex2f(t0) * av[2 * e2];
                    float f1 = ex2f(t1) * av[2 * e2 + 1];
                    zacc[k] += f0 + f1;
                    __half2 hv = __floats2half2_rn(f0, f1);
                    hh[e2] = *reinterpret_cast<uint32_t*>(&hv);
                }
                wu[row * (ROWB / 16) + 8 * h + jj8] =
                    make_uint4(hh[0], hh[1], hh[2], hh[3]);
            }
        };

        load_half(0, 0);

        for (int s = 0; s < NST; s++) {
            const int buf = s & 1;
            if (s >= NBUF) BAR_SYNC(3 + buf);
            const uint32_t bo = (uint32_t)buf * STG_B;
            const int jb = s * TJ;

            const uint32_t obase = smb + bo + W_BYTES;
#pragma unroll
            for (int p = 0; p < 8; p++)
                CP_ASYNC16(obase + odst[p], oTb + osrc[p] + jb);
            CP_COMMIT();

            uint4* wu = reinterpret_cast<uint4*>(sm + bo);
            compute_half(0, s, wu);
#pragma unroll
            for (int h = 1; h < 4; h++) {
                load_half(jb, h);
                compute_half(h, s, wu);
            }

            CP_WAIT0();
            BAR_ARRIVE(1 + buf);
            if (s + 1 < NST) load_half((s + 1) * TJ, 0);
        }

        // Z reduction: sum across the 8 jj8-threads (consecutive lanes)
#pragma unroll
        for (int k = 0; k < 4; k++) {
            zacc[k] += __shfl_xor_sync(0xffffffffu, zacc[k], 1);
            zacc[k] += __shfl_xor_sync(0xffffffffu, zacc[k], 2);
            zacc[k] += __shfl_xor_sync(0xffffffffu, zacc[k], 4);
        }
        if (jj8 == 0) {
#pragma unroll
            for (int k = 0; k < 4; k++)
                Zsh[rgrp + 32 * k] = zacc[k];
        }
        __syncthreads();   // (A)
    }

    __syncthreads();       // (B) aggS ready

    // epilogue: out = aggS(128x64) @ W2(64x64), all 512 threads
    const float* aggS = reinterpret_cast<const float*>(sm);
    const int r0 = tid >> 2;
    const int c0 = tid & 3;
    float res[16];
#pragma unroll
    for (int q = 0; q < 16; q++) res[q] = 0.f;
#pragma unroll 8
    for (int k = 0; k < 64; k++) {
        float a0 = aggS[r0 * 68 + k];
#pragma unroll
        for (int q = 0; q < 16; q++)
            res[q] += a0 * W2s[k * 64 + c0 + 4 * q];
    }
    float* ob = out + (size_t)(b * NN + i_base + r0) * CC;
#pragma unroll
    for (int q = 0; q < 16; q++)
        ob[c0 + 4 * q] = res[q];
}

// ---------------------------------------------------------------------------
extern "C" void kernel_launch(void* const* d_in, const int* in_sizes, int n_in,
                              void* d_out, int out_size)
{
    (void)in_sizes; (void)n_in; (void)out_size;
    const float* X  = (const float*)d_in[0];
    const float* A_ = (const float*)d_in[1];
    const float* W1 = (const float*)d_in[2];
    const float* W2 = (const float*)d_in[3];
    const float* al = (const float*)d_in[4];
    float* out = (float*)d_out;

    cudaFuncSetAttribute(attn_kernel, cudaFuncAttributeMaxDynamicSharedMemorySize,
                         SMEM_BYTES);
    cudaFuncSetAttribute(prep_kernel, cudaFuncAttributeMaxDynamicSharedMemorySize,
                         PREP_SMEM_FLOATS * 4);

    prep_kernel<<<BB * NN / 128, 256, PREP_SMEM_FLOATS * 4>>>(X, W1, al);

    dim3 grid(NN / TI, BB);
    attn_kernel<<<grid, NTHR, SMEM_BYTES>>>(A_, W2, out);
}

// round 15
// speedup vs baseline: 1.1776x; 1.1776x over previous
#include <cuda_runtime.h>
#include <cuda_fp16.h>
#include <cstdint>

#define BB 4
#define NN 4096
#define CC 64
#define TI 128             // i rows per block
#define TJ 64              // j (k-dim) per stage
#define NST (NN / TJ)      // 64 stages
#define NTHR 512           // 16 warps: wm = wid&7 (16 rows), kw = wid>>3 (k half)

// smem per stage: raw A fp32 tile + o half tile + sr
#define AROW 68                            // floats per A row (64 + 4 pad)
#define A_BYTES (TI * AROW * 4)            // 34816
#define OROWB 144                          // bytes per o row (64 + 8 halves)
#define O_BYTES (64 * OROWB)               // 9216
#define SR_BYTES 256
#define STG_B (A_BYTES + O_BYTES + SR_BYTES)   // 44288
#define SM_W2B  (3 * STG_B)                // 132864
#define SM_ZSHB (SM_W2B + 16384)           // 149248
#define SMEM_BYTES (SM_ZSHB + 1024)        // 150272

__device__ __half g_outT[BB * 64 * NN];    // [b][c][n] half
__device__ float  g_sl[BB * NN];
__device__ float  g_sr[BB * NN];

__device__ __forceinline__ float ex2f(float x) {
    float r;
    asm("ex2.approx.f32 %0, %1;" : "=f"(r) : "f"(x));
    return r;
}
__device__ __forceinline__ uint32_t smem_u32(const void* p) {
    uint32_t a;
    asm("{ .reg .u64 t; cvta.to.shared.u64 t, %1; cvt.u32.u64 %0, t; }" : "=r"(a) : "l"(p));
    return a;
}
__device__ __forceinline__ void mma_f16(float d[4], const uint32_t a[4],
                                        uint32_t b0, uint32_t b1) {
    asm volatile(
        "mma.sync.aligned.m16n8k16.row.col.f32.f16.f16.f32 "
        "{%0,%1,%2,%3},{%4,%5,%6,%7},{%8,%9},{%0,%1,%2,%3};"
        : "+f"(d[0]), "+f"(d[1]), "+f"(d[2]), "+f"(d[3])
        : "r"(a[0]), "r"(a[1]), "r"(a[2]), "r"(a[3]), "r"(b0), "r"(b1));
}
#define LDSM4(r, a) \
    asm volatile("ldmatrix.sync.aligned.m8n8.x4.shared.b16 {%0,%1,%2,%3}, [%4];" \
        : "=r"((r)[0]), "=r"((r)[1]), "=r"((r)[2]), "=r"((r)[3]) : "r"(a))
#define CP_ASYNC16(dst, src) \
    asm volatile("cp.async.cg.shared.global [%0], [%1], 16;" :: "r"(dst), "l"(src) : "memory")
#define CP_COMMIT() asm volatile("cp.async.commit_group;" ::: "memory")
#define CP_WAIT1()  asm volatile("cp.async.wait_group 1;" ::: "memory")
#define CP_WAITALL() asm volatile("cp.async.wait_group 0;" ::: "memory")

// ---------------------------------------------------------------------------
// prep (R14, proven): out = X@W1; g_outT half transposed (coalesced); sl, sr
// ---------------------------------------------------------------------------
#define HBUF_STRIDE 136
#define PREP_SMEM_FLOATS (4096 + 128 * 65 + 128 + (64 * HBUF_STRIDE) / 2 + 8)
__global__ __launch_bounds__(256) void prep_kernel(
    const float* __restrict__ X, const float* __restrict__ W1,
    const float* __restrict__ alpha)
{
    extern __shared__ float psm[];
    float*  W1s  = psm;
    float*  Xs   = psm + 4096;
    float*  al   = psm + 4096 + 128 * 65;
    float*  ar   = al + 64;
    __half* hbuf = reinterpret_cast<__half*>(ar + 64);

    const int tid = threadIdx.x;
    const int gr0 = blockIdx.x * 128;
    const int b0  = gr0 >> 12;
    const int n0  = gr0 & (NN - 1);

    for (int i = tid; i < 1024; i += 256)
        reinterpret_cast<float4*>(W1s)[i] = reinterpret_cast<const float4*>(W1)[i];
    for (int i = tid; i < 2048; i += 256) {
        int r = i >> 4, q = i & 15;
        float4 v = reinterpret_cast<const float4*>(X + (size_t)(gr0 + r) * CC)[q];
        Xs[r * 65 + 4 * q + 0] = v.x; Xs[r * 65 + 4 * q + 1] = v.y;
        Xs[r * 65 + 4 * q + 2] = v.z; Xs[r * 65 + 4 * q + 3] = v.w;
    }
    if (tid < 64)       al[tid]      = alpha[tid];
    else if (tid < 128) ar[tid - 64] = alpha[tid];
    __syncthreads();

    const int r  = tid >> 2;
    const int c0 = tid & 3;

    float acc0[16], acc1[16];
#pragma unroll
    for (int q = 0; q < 16; q++) { acc0[q] = 0.f; acc1[q] = 0.f; }
    const float4* W1v = reinterpret_cast<const float4*>(W1s);
#pragma unroll 4
    for (int k = 0; k < 64; k++) {
        float x0 = Xs[r * 65 + k];
        float x1 = Xs[(r + 64) * 65 + k];
#pragma unroll
        for (int h = 0; h < 4; h++) {
            float4 wv = W1v[k * 16 + 4 * c0 + h];
            acc0[4 * h + 0] += x0 * wv.x; acc1[4 * h + 0] += x1 * wv.x;
            acc0[4 * h + 1] += x0 * wv.y; acc1[4 * h + 1] += x1 * wv.y;
            acc0[4 * h + 2] += x0 * wv.z; acc1[4 * h + 2] += x1 * wv.z;
            acc0[4 * h + 3] += x0 * wv.w; acc1[4 * h + 3] += x1 * wv.w;
        }
    }

    float vl0 = 0.f, vr0 = 0.f, vl1 = 0.f, vr1 = 0.f;
#pragma unroll
    for (int q = 0; q < 16; q++) {
        float a_ = al[16 * c0 + q], r_ = ar[16 * c0 + q];
        vl0 += acc0[q] * a_; vr0 += acc0[q] * r_;
        vl1 += acc1[q] * a_; vr1 += acc1[q] * r_;
    }
#pragma unroll
    for (int o = 1; o <= 2; o <<= 1) {
        vl0 += __shfl_xor_sync(0xffffffffu, vl0, o);
        vr0 += __shfl_xor_sync(0xffffffffu, vr0, o);
        vl1 += __shfl_xor_sync(0xffffffffu, vl1, o);
        vr1 += __shfl_xor_sync(0xffffffffu, vr1, o);
    }
    if (c0 == 0) {
        g_sl[gr0 + r] = vl0;       g_sr[gr0 + r] = vr0;
        g_sl[gr0 + r + 64] = vl1;  g_sr[gr0 + r + 64] = vr1;
    }

#pragma unroll
    for (int q = 0; q < 16; q++) {
        int c = 16 * c0 + q;
        hbuf[c * HBUF_STRIDE + r]      = __float2half_rn(acc0[q]);
        hbuf[c * HBUF_STRIDE + r + 64] = __float2half_rn(acc1[q]);
    }
    __syncthreads();

    __half* oT = g_outT + (size_t)b0 * 64 * NN + n0;
#pragma unroll
    for (int p = 0; p < 4; p++) {
        int i = tid + 256 * p;
        int c = i >> 4, q = i & 15;
        uint4 v = *reinterpret_cast<const uint4*>(hbuf + c * HBUF_STRIDE + 8 * q);
        *reinterpret_cast<uint4*>(oT + (size_t)c * NN + 8 * q) = v;
    }
}

// ---------------------------------------------------------------------------
// attn (FUSED): every warp computes its own w fragment in registers.
// 16 warps = 8 wm (16 rows each) x 2 kw (32-wide k half per stage).
// cp.async pipelines raw A (fp32), o (half), sr; 3 buffers, 1 sync/stage.
// ---------------------------------------------------------------------------
__global__ void __launch_bounds__(NTHR, 1) attn_kernel(
    const float* __restrict__ A_, const float* __restrict__ W2,
    float* __restrict__ out)
{
    extern __shared__ char sm[];
    const uint32_t smb = smem_u32(sm);
    float* W2s = reinterpret_cast<float*>(sm + SM_W2B);
    float* Zsh = reinterpret_cast<float*>(sm + SM_ZSHB);   // [2][128]

    const int b      = blockIdx.y;
    const int i_base = blockIdx.x * TI;
    const int tid    = threadIdx.x;
    const int lane   = tid & 31, wid = tid >> 5;
    const int wm = wid & 7, kw = wid >> 3;
    const int r = lane >> 2, cq = lane & 3;
    const int row0 = wm * 16 + r;             // rows row0, row0+8

    for (int i = tid; i < 1024; i += NTHR)
        reinterpret_cast<float4*>(W2s)[i] = reinterpret_cast<const float4*>(W2)[i];

    const __half* oTb = g_outT + (size_t)b * 64 * NN;
    const float*  srg = g_sr + b * NN;

    // cp.async source/dst precompute
    uint32_t adst[4]; int asrc[4];
#pragma unroll
    for (int p = 0; p < 4; p++) {
        int ch = tid + NTHR * p;              // 0..2047
        int rr = ch >> 4, c = ch & 15;
        adst[p] = (uint32_t)(rr * (AROW * 4) + 16 * c);
        asrc[p] = (i_base + rr) * NN + 4 * c; // floats
    }
    const int  orow = tid >> 3, oc = tid & 7;
    const uint32_t odst = (uint32_t)(orow * OROWB + 16 * oc);
    const int  osrc = orow * NN + 8 * oc;     // halves

    auto prefetch = [&](int s) {
        const int jb = s * TJ;
        const uint32_t bo = (uint32_t)(s % 3) * STG_B;
#pragma unroll
        for (int p = 0; p < 4; p++)
            CP_ASYNC16(smb + bo + adst[p], A_ + asrc[p] + jb);
        CP_ASYNC16(smb + bo + A_BYTES + odst, oTb + osrc + jb);
        if (tid < 16)
            CP_ASYNC16(smb + bo + A_BYTES + O_BYTES + 16 * tid, srg + jb + 4 * tid);
        CP_COMMIT();
    };

    // per-row constants
    float cl0, cl1; unsigned fl0, fl1;
    {
        float s0 = g_sl[b * NN + i_base + row0];
        float s1 = g_sl[b * NN + i_base + row0 + 8];
        fl0 = (s0 > 0.f); cl0 = fabsf(s0) * 1.44269504f;
        fl1 = (s1 > 0.f); cl1 = fabsf(s1) * 1.44269504f;
    }

    // B ldmatrix lane offset (proven pattern, OROWB=144)
    const uint32_t boff = (uint32_t)((((lane & 7) + ((lane >> 4) & 1) * 8)) * OROWB
                                     + ((lane >> 3) & 1) * 16);

    float acc[8][4];
#pragma unroll
    for (int nt = 0; nt < 8; nt++)
#pragma unroll
        for (int e = 0; e < 4; e++) acc[nt][e] = 0.f;
    float zacc0 = 0.f, zacc1 = 0.f;

    prefetch(0);
    prefetch(1);
    __syncthreads();   // also covers W2s

    for (int s = 0; s < NST; s++) {
        if (s == NST - 1) { CP_WAITALL(); } else { CP_WAIT1(); }
        __syncthreads();
        if (s + 2 < NST) prefetch(s + 2);

        const uint32_t bo = (uint32_t)(s % 3) * STG_B;
        const float* As  = reinterpret_cast<const float*>(sm + bo);
        const float* srS = reinterpret_cast<const float*>(sm + bo + A_BYTES + O_BYTES);
        const uint32_t wB = smb + bo + A_BYTES + boff;
        const int jb = s * TJ;
        const bool diag = ((unsigned)(jb - i_base) < (unsigned)TI);
        const int d0 = (i_base + row0) - jb;      // valid only when diag

#pragma unroll
        for (int ks = 0; ks < 2; ks++) {
            const int kl = kw * 32 + ks * 16 + 2 * cq;

            float2 a_rl = *reinterpret_cast<const float2*>(As + row0 * AROW + kl);
            float2 a_rh = *reinterpret_cast<const float2*>(As + row0 * AROW + kl + 8);
            float2 a_8l = *reinterpret_cast<const float2*>(As + (row0 + 8) * AROW + kl);
            float2 a_8h = *reinterpret_cast<const float2*>(As + (row0 + 8) * AROW + kl + 8);
            float2 s_lo = *reinterpret_cast<const float2*>(srS + kl);
            float2 s_hi = *reinterpret_cast<const float2*>(srS + kl + 8);

            if (diag) {
                if (d0 == kl)          a_rl.x = 1.f;
                else if (d0 == kl + 1) a_rl.y = 1.f;
                else if (d0 == kl + 8) a_rh.x = 1.f;
                else if (d0 == kl + 9) a_rh.y = 1.f;
                const int d8 = d0 + 8;
                if (d8 == kl)          a_8l.x = 1.f;
                else if (d8 == kl + 1) a_8l.y = 1.f;
                else if (d8 == kl + 8) a_8h.x = 1.f;
                else if (d8 == kl + 9) a_8h.y = 1.f;
            }

            float lp0 = fmaxf(s_lo.x, 0.01f * s_lo.x), lm0 = fmaxf(-s_lo.x, -0.01f * s_lo.x);
            float lp1 = fmaxf(s_lo.y, 0.01f * s_lo.y), lm1 = fmaxf(-s_lo.y, -0.01f * s_lo.y);
            float lp2 = fmaxf(s_hi.x, 0.01f * s_hi.x), lm2 = fmaxf(-s_hi.x, -0.01f * s_hi.x);
            float lp3 = fmaxf(s_hi.y, 0.01f * s_hi.y), lm3 = fmaxf(-s_hi.y, -0.01f * s_hi.y);

            float f00 = ex2f(cl0 * (fl0 ? lp0 : lm0)) * a_rl.x;
            float f01 = ex2f(cl0 * (fl0 ? lp1 : lm1)) * a_rl.y;
            float f02 = ex2f(cl0 * (fl0 ? lp2 : lm2)) * a_rh.x;
            float f03 = ex2f(cl0 * (fl0 ? lp3 : lm3)) * a_rh.y;
            float f10 = ex2f(cl1 * (fl1 ? lp0 : lm0)) * a_8l.x;
            float f11 = ex2f(cl1 * (fl1 ? lp1 : lm1)) * a_8l.y;
            float f12 = ex2f(cl1 * (fl1 ? lp2 : lm2)) * a_8h.x;
            float f13 = ex2f(cl1 * (fl1 ? lp3 : lm3)) * a_8h.y;

            zacc0 += (f00 + f01) + (f02 + f03);
            zacc1 += (f10 + f11) + (f12 + f13);

            uint32_t a[4];
            {
                __half2 h0 = __floats2half2_rn(f00, f01);
                __half2 h1 = __floats2half2_rn(f10, f11);
                __half2 h2 = __floats2half2_rn(f02, f03);
                __half2 h3 = __floats2half2_rn(f12, f13);
                a[0] = *reinterpret_cast<uint32_t*>(&h0);
                a[1] = *reinterpret_cast<uint32_t*>(&h1);
                a[2] = *reinterpret_cast<uint32_t*>(&h2);
                a[3] = *reinterpret_cast<uint32_t*>(&h3);
            }

            const uint32_t ko = (uint32_t)(kw * 64 + ks * 32);
            uint32_t bb[16];
            LDSM4(bb + 0,  wB + ko);
            LDSM4(bb + 4,  wB + 16 * OROWB + ko);
            LDSM4(bb + 8,  wB + 32 * OROWB + ko);
            LDSM4(bb + 12, wB + 48 * OROWB + ko);
#pragma unroll
            for (int g = 0; g < 4; g++) {
                mma_f16(acc[2 * g],     a, bb[4 * g],     bb[4 * g + 1]);
                mma_f16(acc[2 * g + 1], a, bb[4 * g + 2], bb[4 * g + 3]);
            }
        }
    }

    // Z: reduce over cq lanes (cols), per kw half
    zacc0 += __shfl_xor_sync(0xffffffffu, zacc0, 1);
    zacc0 += __shfl_xor_sync(0xffffffffu, zacc0, 2);
    zacc1 += __shfl_xor_sync(0xffffffffu, zacc1, 1);
    zacc1 += __shfl_xor_sync(0xffffffffu, zacc1, 2);
    if (cq == 0) {
        Zsh[kw * 128 + row0]     = zacc0;
        Zsh[kw * 128 + row0 + 8] = zacc1;
    }
    __syncthreads();

    float* aggS = reinterpret_cast<float*>(sm);   // 128 x 68, reuse buf0
    if (kw == 1) {
#pragma unroll
        for (int nt = 0; nt < 8; nt++) {
            int col = 8 * nt + 2 * cq;
            *reinterpret_cast<float2*>(aggS + row0 * 68 + col) =
                make_float2(acc[nt][0], acc[nt][1]);
            *reinterpret_cast<float2*>(aggS + (row0 + 8) * 68 + col) =
                make_float2(acc[nt][2], acc[nt][3]);
        }
    }
    __syncthreads();
    if (kw == 0) {
        float z0 = 1.0f / (Zsh[row0] + Zsh[128 + row0]);
        float z1 = 1.0f / (Zsh[row0 + 8] + Zsh[128 + row0 + 8]);
#pragma unroll
        for (int nt = 0; nt < 8; nt++) {
            int col = 8 * nt + 2 * cq;
            float2 p0 = *reinterpret_cast<const float2*>(aggS + row0 * 68 + col);
            float2 p1 = *reinterpret_cast<const float2*>(aggS + (row0 + 8) * 68 + col);
            *reinterpret_cast<float2*>(aggS + row0 * 68 + col) =
                make_float2((acc[nt][0] + p0.x) * z0, (acc[nt][1] + p0.y) * z0);
            *reinterpret_cast<float2*>(aggS + (row0 + 8) * 68 + col) =
                make_float2((acc[nt][2] + p1.x) * z1, (acc[nt][3] + p1.y) * z1);
        }
    }
    __syncthreads();

    // epilogue: out = aggS(128x64) @ W2(64x64)
    const int r0 = tid >> 2;
    const int c0 = tid & 3;
    float res[16];
#pragma unroll
    for (int q = 0; q < 16; q++) res[q] = 0.f;
#pragma unroll 8
    for (int k = 0; k < 64; k++) {
        float a0 = aggS[r0 * 68 + k];
#pragma unroll
        for (int q = 0; q < 16; q++)
            res[q] += a0 * W2s[k * 64 + c0 + 4 * q];
    }
    float* ob = out + (size_t)(b * NN + i_base + r0) * CC;
#pragma unroll
    for (int q = 0; q < 16; q++)
        ob[c0 + 4 * q] = res[q];
}

// ---------------------------------------------------------------------------
extern "C" void kernel_launch(void* const* d_in, const int* in_sizes, int n_in,
                              void* d_out, int out_size)
{
    (void)in_sizes; (void)n_in; (void)out_size;
    const float* X  = (const float*)d_in[0];
    const float* A_ = (const float*)d_in[1];
    const float* W1 = (const float*)d_in[2];
    const float* W2 = (const float*)d_in[3];
    const float* al = (const float*)d_in[4];
    float* out = (float*)d_out;

    cudaFuncSetAttribute(attn_kernel, cudaFuncAttributeMaxDynamicSharedMemorySize,
                         SMEM_BYTES);
    cudaFuncSetAttribute(prep_kernel, cudaFuncAttributeMaxDynamicSharedMemorySize,
                         PREP_SMEM_FLOATS * 4);

    prep_kernel<<<BB * NN / 128, 256, PREP_SMEM_FLOATS * 4>>>(X, W1, al);

    dim3 grid(NN / TI, BB);
    attn_kernel<<<grid, NTHR, SMEM_BYTES>>>(A_, W2, out);
}

// round 16
// speedup vs baseline: 1.2022x; 1.0208x over previous
#include <cuda_runtime.h>
#include <cuda_fp16.h>
#include <cstdint>

#define BB 4
#define NN 4096
#define CC 64
#define TI 128             // i rows per block
#define TJ 128             // j (k-dim) per stage
#define NST (NN / TJ)      // 32 stages
#define NTHR 512           // 16 warps: wm = wid&7 (16 rows), kw = wid>>3 (64-wide k half)

// smem per stage: raw A fp32 tile + o half tile + sr
#define AROW 132                           // floats per A row (128 + 4 pad)
#define A_BYTES (TI * AROW * 4)            // 67584
#define OROWB 272                          // bytes per o row (128 + 8 halves); 272%128=16
#define O_BYTES (64 * OROWB)               // 17408
#define SR_BYTES 512
#define STG_B (A_BYTES + O_BYTES + SR_BYTES)   // 85504
#define SM_W2B  (2 * STG_B)                // 171008
#define SM_ZSHB (SM_W2B + 16384)           // 187392
#define SMEM_BYTES (SM_ZSHB + 1024)        // 188416

__device__ __half g_outT[BB * 64 * NN];    // [b][c][n] half
__device__ float  g_sl[BB * NN];
__device__ float  g_sr[BB * NN];

__device__ __forceinline__ float ex2f(float x) {
    float r;
    asm("ex2.approx.f32 %0, %1;" : "=f"(r) : "f"(x));
    return r;
}
__device__ __forceinline__ uint32_t smem_u32(const void* p) {
    uint32_t a;
    asm("{ .reg .u64 t; cvta.to.shared.u64 t, %1; cvt.u32.u64 %0, t; }" : "=r"(a) : "l"(p));
    return a;
}
__device__ __forceinline__ void mma_f16(float d[4], const uint32_t a[4],
                                        uint32_t b0, uint32_t b1) {
    asm volatile(
        "mma.sync.aligned.m16n8k16.row.col.f32.f16.f16.f32 "
        "{%0,%1,%2,%3},{%4,%5,%6,%7},{%8,%9},{%0,%1,%2,%3};"
        : "+f"(d[0]), "+f"(d[1]), "+f"(d[2]), "+f"(d[3])
        : "r"(a[0]), "r"(a[1]), "r"(a[2]), "r"(a[3]), "r"(b0), "r"(b1));
}
#define LDSM4(r, a) \
    asm volatile("ldmatrix.sync.aligned.m8n8.x4.shared.b16 {%0,%1,%2,%3}, [%4];" \
        : "=r"((r)[0]), "=r"((r)[1]), "=r"((r)[2]), "=r"((r)[3]) : "r"(a))
#define CP_ASYNC16(dst, src) \
    asm volatile("cp.async.cg.shared.global [%0], [%1], 16;" :: "r"(dst), "l"(src) : "memory")
#define CP_COMMIT() asm volatile("cp.async.commit_group;" ::: "memory")
#define CP_WAITALL() asm volatile("cp.async.wait_group 0;" ::: "memory")

// ---------------------------------------------------------------------------
// prep (R14/R15, proven): out = X@W1; g_outT half transposed (coalesced); sl, sr
// ---------------------------------------------------------------------------
#define HBUF_STRIDE 136
#define PREP_SMEM_FLOATS (4096 + 128 * 65 + 128 + (64 * HBUF_STRIDE) / 2 + 8)
__global__ __launch_bounds__(256) void prep_kernel(
    const float* __restrict__ X, const float* __restrict__ W1,
    const float* __restrict__ alpha)
{
    extern __shared__ float psm[];
    float*  W1s  = psm;
    float*  Xs   = psm + 4096;
    float*  al   = psm + 4096 + 128 * 65;
    float*  ar   = al + 64;
    __half* hbuf = reinterpret_cast<__half*>(ar + 64);

    const int tid = threadIdx.x;
    const int gr0 = blockIdx.x * 128;
    const int b0  = gr0 >> 12;
    const int n0  = gr0 & (NN - 1);

    for (int i = tid; i < 1024; i += 256)
        reinterpret_cast<float4*>(W1s)[i] = reinterpret_cast<const float4*>(W1)[i];
    for (int i = tid; i < 2048; i += 256) {
        int r = i >> 4, q = i & 15;
        float4 v = reinterpret_cast<const float4*>(X + (size_t)(gr0 + r) * CC)[q];
        Xs[r * 65 + 4 * q + 0] = v.x; Xs[r * 65 + 4 * q + 1] = v.y;
        Xs[r * 65 + 4 * q + 2] = v.z; Xs[r * 65 + 4 * q + 3] = v.w;
    }
    if (tid < 64)       al[tid]      = alpha[tid];
    else if (tid < 128) ar[tid - 64] = alpha[tid];
    __syncthreads();

    const int r  = tid >> 2;
    const int c0 = tid & 3;

    float acc0[16], acc1[16];
#pragma unroll
    for (int q = 0; q < 16; q++) { acc0[q] = 0.f; acc1[q] = 0.f; }
    const float4* W1v = reinterpret_cast<const float4*>(W1s);
#pragma unroll 4
    for (int k = 0; k < 64; k++) {
        float x0 = Xs[r * 65 + k];
        float x1 = Xs[(r + 64) * 65 + k];
#pragma unroll
        for (int h = 0; h < 4; h++) {
            float4 wv = W1v[k * 16 + 4 * c0 + h];
            acc0[4 * h + 0] += x0 * wv.x; acc1[4 * h + 0] += x1 * wv.x;
            acc0[4 * h + 1] += x0 * wv.y; acc1[4 * h + 1] += x1 * wv.y;
            acc0[4 * h + 2] += x0 * wv.z; acc1[4 * h + 2] += x1 * wv.z;
            acc0[4 * h + 3] += x0 * wv.w; acc1[4 * h + 3] += x1 * wv.w;
        }
    }

    float vl0 = 0.f, vr0 = 0.f, vl1 = 0.f, vr1 = 0.f;
#pragma unroll
    for (int q = 0; q < 16; q++) {
        float a_ = al[16 * c0 + q], r_ = ar[16 * c0 + q];
        vl0 += acc0[q] * a_; vr0 += acc0[q] * r_;
        vl1 += acc1[q] * a_; vr1 += acc1[q] * r_;
    }
#pragma unroll
    for (int o = 1; o <= 2; o <<= 1) {
        vl0 += __shfl_xor_sync(0xffffffffu, vl0, o);
        vr0 += __shfl_xor_sync(0xffffffffu, vr0, o);
        vl1 += __shfl_xor_sync(0xffffffffu, vl1, o);
        vr1 += __shfl_xor_sync(0xffffffffu, vr1, o);
    }
    if (c0 == 0) {
        g_sl[gr0 + r] = vl0;       g_sr[gr0 + r] = vr0;
        g_sl[gr0 + r + 64] = vl1;  g_sr[gr0 + r + 64] = vr1;
    }

#pragma unroll
    for (int q = 0; q < 16; q++) {
        int c = 16 * c0 + q;
        hbuf[c * HBUF_STRIDE + r]      = __float2half_rn(acc0[q]);
        hbuf[c * HBUF_STRIDE + r + 64] = __float2half_rn(acc1[q]);
    }
    __syncthreads();

    __half* oT = g_outT + (size_t)b0 * 64 * NN + n0;
#pragma unroll
    for (int p = 0; p < 4; p++) {
        int i = tid + 256 * p;
        int c = i >> 4, q = i & 15;
        uint4 v = *reinterpret_cast<const uint4*>(hbuf + c * HBUF_STRIDE + 8 * q);
        *reinterpret_cast<uint4*>(oT + (size_t)c * NN + 8 * q) = v;
    }
}

// ---------------------------------------------------------------------------
// attn (FUSED, TJ=128): every warp computes its own w fragment in registers.
// 16 warps = 8 wm (16 rows each) x 2 kw (64-wide k half per stage).
// cp.async pipeline: prefetch(s+1) after stage-s barrier; NBUF=2.
// ---------------------------------------------------------------------------
__global__ void __launch_bounds__(NTHR, 1) attn_kernel(
    const float* __restrict__ A_, const float* __restrict__ W2,
    float* __restrict__ out)
{
    extern __shared__ char sm[];
    const uint32_t smb = smem_u32(sm);
    float* W2s = reinterpret_cast<float*>(sm + SM_W2B);
    float* Zsh = reinterpret_cast<float*>(sm + SM_ZSHB);   // [2][128]

    const int b      = blockIdx.y;
    const int i_base = blockIdx.x * TI;
    const int tid    = threadIdx.x;
    const int lane   = tid & 31, wid = tid >> 5;
    const int wm = wid & 7, kw = wid >> 3;
    const int r = lane >> 2, cq = lane & 3;
    const int row0 = wm * 16 + r;             // rows row0, row0+8

    for (int i = tid; i < 1024; i += NTHR)
        reinterpret_cast<float4*>(W2s)[i] = reinterpret_cast<const float4*>(W2)[i];

    const __half* oTb = g_outT + (size_t)b * 64 * NN;
    const float*  srg = g_sr + b * NN;

    // cp.async source/dst precompute
    uint32_t adst[8]; int asrc[8];
#pragma unroll
    for (int p = 0; p < 8; p++) {
        int ch = tid + NTHR * p;              // 0..4095
        int rr = ch >> 5, c = ch & 31;        // 32 x 16B chunks per A row
        adst[p] = (uint32_t)(rr * (AROW * 4) + 16 * c);
        asrc[p] = (i_base + rr) * NN + 4 * c; // floats
    }
    uint32_t odst[2]; int osrc[2];
#pragma unroll
    for (int p = 0; p < 2; p++) {
        int ch = tid + NTHR * p;              // 0..1023
        int rr = ch >> 4, c = ch & 15;        // 16 x 16B data chunks per o row
        odst[p] = (uint32_t)(rr * OROWB + 16 * c);
        osrc[p] = rr * NN + 8 * c;            // halves
    }

    auto prefetch = [&](int s) {
        const int jb = s * TJ;
        const uint32_t bo = (uint32_t)(s & 1) * STG_B;
#pragma unroll
        for (int p = 0; p < 8; p++)
            CP_ASYNC16(smb + bo + adst[p], A_ + asrc[p] + jb);
#pragma unroll
        for (int p = 0; p < 2; p++)
            CP_ASYNC16(smb + bo + A_BYTES + odst[p], oTb + osrc[p] + jb);
        if (tid < 32)
            CP_ASYNC16(smb + bo + A_BYTES + O_BYTES + 16 * tid, srg + jb + 4 * tid);
        CP_COMMIT();
    };

    // per-row constants
    float cl0, cl1; unsigned fl0, fl1;
    {
        float s0 = g_sl[b * NN + i_base + row0];
        float s1 = g_sl[b * NN + i_base + row0 + 8];
        fl0 = (s0 > 0.f); cl0 = fabsf(s0) * 1.44269504f;
        fl1 = (s1 > 0.f); cl1 = fabsf(s1) * 1.44269504f;
    }

    // B ldmatrix lane offset (OROWB % 128 == 16 -> conflict-free, proven)
    const uint32_t boff = (uint32_t)((((lane & 7) + ((lane >> 4) & 1) * 8)) * OROWB
                                     + ((lane >> 3) & 1) * 16);

    float acc[8][4];
#pragma unroll
    for (int nt = 0; nt < 8; nt++)
#pragma unroll
        for (int e = 0; e < 4; e++) acc[nt][e] = 0.f;
    float zacc0 = 0.f, zacc1 = 0.f;

    prefetch(0);
    __syncthreads();   // covers W2s store ordering for all threads

    for (int s = 0; s < NST; s++) {
        CP_WAITALL();
        __syncthreads();
        if (s + 1 < NST) prefetch(s + 1);   // load s+1 overlaps compute s

        const uint32_t bo = (uint32_t)(s & 1) * STG_B;
        const float* As  = reinterpret_cast<const float*>(sm + bo);
        const float* srS = reinterpret_cast<const float*>(sm + bo + A_BYTES + O_BYTES);
        const uint32_t wB = smb + bo + A_BYTES + boff;
        const int jb = s * TJ;
        const bool diag = (jb == i_base);
        const int d0 = row0;                 // diag col (valid when diag)

#pragma unroll
        for (int ks = 0; ks < 4; ks++) {
            const int kl = kw * 64 + ks * 16 + 2 * cq;

            float2 a_rl = *reinterpret_cast<const float2*>(As + row0 * AROW + kl);
            float2 a_rh = *reinterpret_cast<const float2*>(As + row0 * AROW + kl + 8);
            float2 a_8l = *reinterpret_cast<const float2*>(As + (row0 + 8) * AROW + kl);
            float2 a_8h = *reinterpret_cast<const float2*>(As + (row0 + 8) * AROW + kl + 8);
            float2 s_lo = *reinterpret_cast<const float2*>(srS + kl);
            float2 s_hi = *reinterpret_cast<const float2*>(srS + kl + 8);

            if (diag) {
                if (d0 == kl)          a_rl.x = 1.f;
                else if (d0 == kl + 1) a_rl.y = 1.f;
                else if (d0 == kl + 8) a_rh.x = 1.f;
                else if (d0 == kl + 9) a_rh.y = 1.f;
                const int d8 = d0 + 8;
                if (d8 == kl)          a_8l.x = 1.f;
                else if (d8 == kl + 1) a_8l.y = 1.f;
                else if (d8 == kl + 8) a_8h.x = 1.f;
                else if (d8 == kl + 9) a_8h.y = 1.f;
            }

            float lp0 = fmaxf(s_lo.x, 0.01f * s_lo.x), lm0 = fmaxf(-s_lo.x, -0.01f * s_lo.x);
            float lp1 = fmaxf(s_lo.y, 0.01f * s_lo.y), lm1 = fmaxf(-s_lo.y, -0.01f * s_lo.y);
            float lp2 = fmaxf(s_hi.x, 0.01f * s_hi.x), lm2 = fmaxf(-s_hi.x, -0.01f * s_hi.x);
            float lp3 = fmaxf(s_hi.y, 0.01f * s_hi.y), lm3 = fmaxf(-s_hi.y, -0.01f * s_hi.y);

            float f00 = ex2f(cl0 * (fl0 ? lp0 : lm0)) * a_rl.x;
            float f01 = ex2f(cl0 * (fl0 ? lp1 : lm1)) * a_rl.y;
            float f02 = ex2f(cl0 * (fl0 ? lp2 : lm2)) * a_rh.x;
            float f03 = ex2f(cl0 * (fl0 ? lp3 : lm3)) * a_rh.y;
            float f10 = ex2f(cl1 * (fl1 ? lp0 : lm0)) * a_8l.x;
            float f11 = ex2f(cl1 * (fl1 ? lp1 : lm1)) * a_8l.y;
            float f12 = ex2f(cl1 * (fl1 ? lp2 : lm2)) * a_8h.x;
            float f13 = ex2f(cl1 * (fl1 ? lp3 : lm3)) * a_8h.y;

            zacc0 += (f00 + f01) + (f02 + f03);
            zacc1 += (f10 + f11) + (f12 + f13);

            uint32_t a[4];
            {
                __half2 h0 = __floats2half2_rn(f00, f01);
                __half2 h1 = __floats2half2_rn(f10, f11);
                __half2 h2 = __floats2half2_rn(f02, f03);
                __half2 h3 = __floats2half2_rn(f12, f13);
                a[0] = *reinterpret_cast<uint32_t*>(&h0);
                a[1] = *reinterpret_cast<uint32_t*>(&h1);
                a[2] = *reinterpret_cast<uint32_t*>(&h2);
                a[3] = *reinterpret_cast<uint32_t*>(&h3);
            }

            const uint32_t ko = (uint32_t)(kw * 128 + ks * 32);
            uint32_t bb[16];
            LDSM4(bb + 0,  wB + ko);
            LDSM4(bb + 4,  wB + 16 * OROWB + ko);
            LDSM4(bb + 8,  wB + 32 * OROWB + ko);
            LDSM4(bb + 12, wB + 48 * OROWB + ko);
#pragma unroll
            for (int g = 0; g < 4; g++) {
                mma_f16(acc[2 * g],     a, bb[4 * g],     bb[4 * g + 1]);
                mma_f16(acc[2 * g + 1], a, bb[4 * g + 2], bb[4 * g + 3]);
            }
        }
    }

    // Z: reduce over cq lanes (cols), per kw half
    zacc0 += __shfl_xor_sync(0xffffffffu, zacc0, 1);
    zacc0 += __shfl_xor_sync(0xffffffffu, zacc0, 2);
    zacc1 += __shfl_xor_sync(0xffffffffu, zacc1, 1);
    zacc1 += __shfl_xor_sync(0xffffffffu, zacc1, 2);
    if (cq == 0) {
        Zsh[kw * 128 + row0]     = zacc0;
        Zsh[kw * 128 + row0 + 8] = zacc1;
    }
    __syncthreads();

    float* aggS = reinterpret_cast<float*>(sm);   // 128 x 68, reuse buf0
    if (kw == 1) {
#pragma unroll
        for (int nt = 0; nt < 8; nt++) {
            int col = 8 * nt + 2 * cq;
            *reinterpret_cast<float2*>(aggS + row0 * 68 + col) =
                make_float2(acc[nt][0], acc[nt][1]);
            *reinterpret_cast<float2*>(aggS + (row0 + 8) * 68 + col) =
                make_float2(acc[nt][2], acc[nt][3]);
        }
    }
    __syncthreads();
    if (kw == 0) {
        float z0 = 1.0f / (Zsh[row0] + Zsh[128 + row0]);
        float z1 = 1.0f / (Zsh[row0 + 8] + Zsh[128 + row0 + 8]);
#pragma unroll
        for (int nt = 0; nt < 8; nt++) {
            int col = 8 * nt + 2 * cq;
            float2 p0 = *reinterpret_cast<const float2*>(aggS + row0 * 68 + col);
            float2 p1 = *reinterpret_cast<const float2*>(aggS + (row0 + 8) * 68 + col);
            *reinterpret_cast<float2*>(aggS + row0 * 68 + col) =
                make_float2((acc[nt][0] + p0.x) * z0, (acc[nt][1] + p0.y) * z0);
            *reinterpret_cast<float2*>(aggS + (row0 + 8) * 68 + col) =
                make_float2((acc[nt][2] + p1.x) * z1, (acc[nt][3] + p1.y) * z1);
        }
    }
    __syncthreads();

    // epilogue: out = aggS(128x64) @ W2(64x64)
    const int r0 = tid >> 2;
    const int c0 = tid & 3;
    float res[16];
#pragma unroll
    for (int q = 0; q < 16; q++) res[q] = 0.f;
#pragma unroll 8
    for (int k = 0; k < 64; k++) {
        float a0 = aggS[r0 * 68 + k];
#pragma unroll
        for (int q = 0; q < 16; q++)
            res[q] += a0 * W2s[k * 64 + c0 + 4 * q];
    }
    float* ob = out + (size_t)(b * NN + i_base + r0) * CC;
#pragma unroll
    for (int q = 0; q < 16; q++)
        ob[c0 + 4 * q] = res[q];
}

// ---------------------------------------------------------------------------
extern "C" void kernel_launch(void* const* d_in, const int* in_sizes, int n_in,
                              void* d_out, int out_size)
{
    (void)in_sizes; (void)n_in; (void)out_size;
    const float* X  = (const float*)d_in[0];
    const float* A_ = (const float*)d_in[1];
    const float* W1 = (const float*)d_in[2];
    const float* W2 = (const float*)d_in[3];
    const float* al = (const float*)d_in[4];
    float* out = (float*)d_out;

    cudaFuncSetAttribute(attn_kernel, cudaFuncAttributeMaxDynamicSharedMemorySize,
                         SMEM_BYTES);
    cudaFuncSetAttribute(prep_kernel, cudaFuncAttributeMaxDynamicSharedMemorySize,
                         PREP_SMEM_FLOATS * 4);

    prep_kernel<<<BB * NN / 128, 256, PREP_SMEM_FLOATS * 4>>>(X, W1, al);

    dim3 grid(NN / TI, BB);
    attn_kernel<<<grid, NTHR, SMEM_BYTES>>>(A_, W2, out);
}